// round 15
// baseline (speedup 1.0000x reference)
#include <cuda_runtime.h>
#include <cuda_fp16.h>
#include <math.h>

// Problem constants
static constexpr int NB = 8, NC = 256, NH = 128, NW = 128;
static constexpr int HW = NH * NW;
static constexpr float EPSF = 1e-8f;

static constexpr int CSPLIT = 4;           // channel slices
static constexpr int CPG = NC / CSPLIT;    // 64 channels per block
static constexpr int CC = 8;               // channels per staged chunk
static constexpr int NCHUNK = CPG / CC;    // 8
static constexpr int SROW = 36;            // smem floats per halo row ([-2,34))
static constexpr int SPLANE = 18 * SROW;   // 648 floats per channel plane
static constexpr int NSTRIP = 64;          // epilogue: 2-row strips

typedef unsigned long long ull;
typedef unsigned int u32;

// Device scratch (dense writes only)
__device__ u32   g_dotsh[CSPLIT][(size_t)NB * HW * 6];  // 12 halves per px
__device__ float g_nsq4[(size_t)NB * HW * 4];           // [pixel][slice]
__device__ float g_stotal[NB * NSTRIP];
__device__ int   g_scnt [NB * NSTRIP];
__device__ int   g_sinc [NB * NSTRIP];
__device__ int   g_arrive;                 // zero-init; reset by last block

__device__ __forceinline__ ull pk(float lo, float hi) {
    ull r;
    asm("mov.b64 %0, {%1, %2};" : "=l"(r) : "f"(lo), "f"(hi));
    return r;
}
__device__ __forceinline__ ull u2(float2 v) { return pk(v.x, v.y); }
__device__ __forceinline__ void upk(ull v, float& lo, float& hi) {
    asm("mov.b64 {%0, %1}, %2;" : "=f"(lo), "=f"(hi) : "l"(v));
}
__device__ __forceinline__ void fma2(ull& a, ull x, ull y) {
    asm("fma.rn.f32x2 %0, %1, %2, %0;" : "+l"(a) : "l"(x), "l"(y));
}
__device__ __forceinline__ u32 h2(float a, float b) {
    __half2 h = __floats2half2_rn(a, b);
    return *(u32*)&h;
}
__device__ __forceinline__ void cpa8(u32 dst, const float* src) {
    asm volatile("cp.async.ca.shared.global [%0], [%1], 8;"
                 :: "r"(dst), "l"(src) : "memory");
}

// ---------------------------------------------------------------------------
// Kernel 1: partial dots + norm^2. cp.async (8B) double-buffered planes.
// Tile 16x32 core (halo 18x[-2,34)), 128 threads = 2x2 px quads, 5 blocks/SM.
// Grid (4, 8, NB*CSPLIT) = 1024 blocks.
// ---------------------------------------------------------------------------
__global__ __launch_bounds__(128, 5) void partial_kernel(const float* __restrict__ er)
{
    __shared__ float sbuf[2][CC * SPLANE];   // 2 x 20736 B = 41472 B

    const int b  = blockIdx.z >> 2;
    const int cs = blockIdx.z & 3;
    const int h0 = blockIdx.y * 16;
    const int w0 = blockIdx.x * 32;
    const int tid = threadIdx.x;
    const int qx = tid & 15;
    const int qy = tid >> 4;

    const float* erblk = er + ((size_t)b * NC + cs * CPG) * HW;

    // ---- per-thread staging jobs: (ch,row) pairs; 144 jobs over 128 threads ----
    // job 1: rp = tid; job 2 (threads tid%8==0): rp2 = 128 + tid/8
    const int ch1  = tid / 18;
    const int row1 = tid - ch1 * 18;
    const int gb1  = (h0 + row1) * NW + w0 - 2;           // flat src start (col -2)
    const int sb1f = ch1 * SPLANE + row1 * SROW;          // smem float index
    const bool safe1 = (gb1 >= 0) && (gb1 + 34 <= HW - 2);

    const bool has2 = ((tid & 7) == 0);
    const int rp2  = 128 + (tid >> 3);                    // 128..143
    const int ch2  = 7;                                   // rp2/18 == 7 always
    const int row2 = rp2 - 126;                           // 2..17
    const int gb2  = (h0 + row2) * NW + w0 - 2;
    const int sb2f = ch2 * SPLANE + row2 * SROW;
    const bool safe2 = (gb2 >= 0) && (gb2 + 34 <= HW - 2);

    u32 sbB0 = (u32)__cvta_generic_to_shared(&sbuf[0][0]);
    u32 sbB1 = (u32)__cvta_generic_to_shared(&sbuf[1][0]);

#define ROWCOPY(GP, GB, SA, SAFE) {                                            \
        if (SAFE) {                                                            \
            _Pragma("unroll")                                                  \
            for (int g = 0; g < 18; g++)                                       \
                cpa8((SA) + 8 * g, (GP) + (GB) + 2 * g);                       \
        } else {                                                               \
            _Pragma("unroll")                                                  \
            for (int g = 0; g < 18; g++) {                                     \
                int sf = (GB) + 2 * g;                                         \
                sf = sf < 0 ? 0 : (sf > HW - 2 ? HW - 2 : sf);                 \
                cpa8((SA) + 8 * g, (GP) + sf);                                 \
            }                                                                  \
        }                                                                      \
    }

#define ISSUE(CH, SB) {                                                        \
        const float* gp1 = erblk + (size_t)((CH) * CC + ch1) * HW;             \
        ROWCOPY(gp1, gb1, (SB) + sb1f * 4, safe1);                             \
        if (has2) {                                                            \
            const float* gp2 = erblk + (size_t)((CH) * CC + ch2) * HW;         \
            ROWCOPY(gp2, gb2, (SB) + sb2f * 4, safe2);                         \
        }                                                                      \
        asm volatile("cp.async.commit_group;" ::: "memory");                   \
    }

    ull a0[12], a1[12];
#pragma unroll
    for (int d = 0; d < 12; d++) { a0[d] = 0ull; a1[d] = 0ull; }
    ull selfA = 0ull, selfB = 0ull;

    // quad base: pixel rows 2qy..2qy+3, first core col 2qx (halo col 2qx+2)
    const int tboff = (2 * qy) * SROW + (2 * qx + 2);

#define COMPUTE(BUF) {                                                         \
        const float* tb = (BUF) + tboff;                                       \
        _Pragma("unroll")                                                      \
        for (int ch = 0; ch < CC; ch++) {                                      \
            const float* pl = tb + ch * SPLANE;                                \
            float2 F0 = *(const float2*)(pl);                                  \
            float2 F2 = *(const float2*)(pl + 2);                              \
            float2 Gm = *(const float2*)(pl + SROW - 2);                       \
            float2 G0 = *(const float2*)(pl + SROW);                           \
            float2 G2 = *(const float2*)(pl + SROW + 2);                       \
            float2 Hm = *(const float2*)(pl + 2 * SROW - 2);                   \
            float2 H0 = *(const float2*)(pl + 2 * SROW);                       \
            float2 H2 = *(const float2*)(pl + 2 * SROW + 2);                   \
            float2 Km = *(const float2*)(pl + 3 * SROW - 2);                   \
            float2 K0 = *(const float2*)(pl + 3 * SROW);                       \
            float2 K2 = *(const float2*)(pl + 3 * SROW + 2);                   \
            ull PP = u2(F0), QQ = u2(G0);                                      \
            ull pF  = pk(F0.y, F2.x);                                          \
            ull pG1 = pk(Gm.y, G0.x), pG2 = pk(G0.y, G2.x);                    \
            ull pH1 = pk(Hm.y, H0.x), pH2 = pk(H0.y, H2.x);                    \
            ull pK1 = pk(Km.y, K0.x), pK2 = pk(K0.y, K2.x);                    \
            ull uF2 = u2(F2), uGm = u2(Gm), uG2 = u2(G2);                      \
            ull uHm = u2(Hm), uH0 = u2(H0), uH2 = u2(H2);                      \
            ull uKm = u2(Km), uK0 = u2(K0), uK2 = u2(K2);                      \
            fma2(selfA, PP, PP);  fma2(selfB, QQ, QQ);                         \
            fma2(a0[0], PP, pF);  fma2(a0[1], PP, uF2);                        \
            fma2(a0[2], PP, uGm); fma2(a0[3], PP, pG1); fma2(a0[4], PP, QQ);   \
            fma2(a0[5], PP, pG2); fma2(a0[6], PP, uG2);                        \
            fma2(a0[7], PP, uHm); fma2(a0[8], PP, pH1); fma2(a0[9], PP, uH0);  \
            fma2(a0[10], PP, pH2); fma2(a0[11], PP, uH2);                      \
            fma2(a1[0], QQ, pG2); fma2(a1[1], QQ, uG2);                        \
            fma2(a1[2], QQ, uHm); fma2(a1[3], QQ, pH1); fma2(a1[4], QQ, uH0);  \
            fma2(a1[5], QQ, pH2); fma2(a1[6], QQ, uH2);                        \
            fma2(a1[7], QQ, uKm); fma2(a1[8], QQ, pK1); fma2(a1[9], QQ, uK0);  \
            fma2(a1[10], QQ, pK2); fma2(a1[11], QQ, uK2);                      \
        }                                                                      \
    }

    // ---- pipeline: prolog loads 2 chunks, then compute/prefetch overlap ----
    ISSUE(0, sbB0);
    ISSUE(1, sbB1);
#pragma unroll 1
    for (int c = 0; c < NCHUNK; c++) {
        if (c < NCHUNK - 1)
            asm volatile("cp.async.wait_group 1;" ::: "memory");
        else
            asm volatile("cp.async.wait_group 0;" ::: "memory");
        __syncthreads();
        const float* bp = (c & 1) ? &sbuf[1][0] : &sbuf[0][0];
        COMPUTE(bp);
        __syncthreads();
        if (c + 2 < NCHUNK) {
            u32 sb = (c & 1) ? sbB1 : sbB0;
            ISSUE(c + 2, sb);
        }
    }
#undef ISSUE
#undef ROWCOPY
#undef COMPUTE

    // ---- writeback as fp16 (dense; each element written exactly once) ----
    const int p00 = (h0 + 2 * qy) * NW + (w0 + 2 * qx);
    u32* dbase = g_dotsh[cs] + (size_t)b * HW * 6;
    float v0[12], v1[12], v2[12], v3[12];
#pragma unroll
    for (int d = 0; d < 12; d++) {
        upk(a0[d], v0[d], v1[d]);
        upk(a1[d], v2[d], v3[d]);
    }
#define ST12H(P, V) {                                                          \
        u32* dst = dbase + (size_t)(P) * 6;                                    \
        *(uint2*)(dst)     = make_uint2(h2(V[0], V[1]),  h2(V[2],  V[3]));     \
        *(uint2*)(dst + 2) = make_uint2(h2(V[4], V[5]),  h2(V[6],  V[7]));     \
        *(uint2*)(dst + 4) = make_uint2(h2(V[8], V[9]),  h2(V[10], V[11]));    \
    }
    ST12H(p00,          v0);
    ST12H(p00 + 1,      v1);
    ST12H(p00 + NW,     v2);
    ST12H(p00 + NW + 1, v3);
#undef ST12H
    float s0, s1, s2, s3;
    upk(selfA, s0, s1);
    upk(selfB, s2, s3);
    float* nptr = g_nsq4 + ((size_t)b * HW + p00) * 4 + cs;
    nptr[0]           = s0;
    nptr[4]           = s1;
    nptr[NW * 4]      = s2;
    nptr[NW * 4 + 4]  = s3;
}

// ---------------------------------------------------------------------------
// Kernel 2: epilogue + fused finalize. Block = (2-row strip, image), 256 thr.
// Inverse norms; float4 nsq read; fp16 dot partials.  [unchanged from R13]
// ---------------------------------------------------------------------------
__global__ __launch_bounds__(256) void epilogue_kernel(
    const int* __restrict__ seg, const int* __restrict__ gtb,
    float* __restrict__ out)
{
    __shared__ float shN[6 * 132];     // INVERSE norms
    __shared__ int   shL[6 * 132];
    __shared__ float sRf[8];
    __shared__ int   sRc[8], sRi[8], sLast;

    const int strip = blockIdx.x;
    const int b     = blockIdx.y;
    const int h0    = strip * 2;
    const int tid   = threadIdx.x;
    const int* segb = seg + b * HW;
    const int* gtbb = gtb + b * HW;

    // Stage inverse norms + label codes: rows [h0-2, h0+4), cols [-2, 130)
    for (int i = tid; i < 6 * 132; i += 256) {
        int r = i / 132, c = i - r * 132;
        int gh = h0 - 2 + r, gw = c - 2;
        float inv = 1.f;
        int code = 0x7FFF;
        if (gh >= 0 && gh < NH && gw >= 0 && gw < NW) {
            size_t idx = (size_t)b * HW + gh * NW + gw;
            float4 n4 = *(const float4*)(g_nsq4 + idx * 4);
            float ns = (n4.x + n4.y) + (n4.z + n4.w);
            inv = 1.f / fmaxf(sqrtf(ns), EPSF);
            int li = gh * NW + gw;
            int s = segb[li], g = gtbb[li];
            int s0v = (s == 255) ? 0 : s;
            int g0v = (g == 255) ? 0 : g;
            bool fg    = (s0v * g0v > 0);
            bool inter = (gh >= 2 && gh < NH - 2 && gw >= 2 && gw < NW - 2);
            code = (s & 0xFFFF) | ((fg && inter) ? 0x10000 : 0) | (fg ? 0x20000 : 0);
        }
        shN[i] = inv;
        shL[i] = code;
    }
    __syncthreads();

    const int ty = tid >> 7, tx = tid & 127;
    const int p  = (h0 + ty) * NW + tx;

    // Sum the 4 slice dot-partials (fp16 -> fp32)
    float dsum[12];
#pragma unroll
    for (int d = 0; d < 12; d++) dsum[d] = 0.f;
    {
        const size_t off = ((size_t)b * HW + p) * 6;
#pragma unroll
        for (int cs = 0; cs < CSPLIT; cs++) {
            const u32* s = g_dotsh[cs] + off;
            uint2 w0v = *(const uint2*)(s);
            uint2 w1v = *(const uint2*)(s + 2);
            uint2 w2v = *(const uint2*)(s + 4);
            float2 f;
            f = __half22float2(*(__half2*)&w0v.x); dsum[0] += f.x; dsum[1] += f.y;
            f = __half22float2(*(__half2*)&w0v.y); dsum[2] += f.x; dsum[3] += f.y;
            f = __half22float2(*(__half2*)&w1v.x); dsum[4] += f.x; dsum[5] += f.y;
            f = __half22float2(*(__half2*)&w1v.y); dsum[6] += f.x; dsum[7] += f.y;
            f = __half22float2(*(__half2*)&w2v.x); dsum[8] += f.x; dsum[9] += f.y;
            f = __half22float2(*(__half2*)&w2v.y); dsum[10] += f.x; dsum[11] += f.y;
        }
    }

    const int mp = (ty + 2) * 132 + (tx + 2);
    const int dof[12] = {1, 2,
                         132 - 2, 132 - 1, 132, 132 + 1, 132 + 2,
                         264 - 2, 264 - 1, 264, 264 + 1, 264 + 2};

    int pcode = shL[mp];
    float vp  = (float)((pcode >> 16) & 1);
    int   cnt = (pcode >> 16) & 1;
    int   inc = (pcode >> 17) & 1;
    int   sp  = pcode & 0xFFFF;
    float invnp = shN[mp];

    float acc = 0.f;
#pragma unroll
    for (int d = 0; d < 12; d++) {
        int ncode = shL[mp + dof[d]];
        float vn  = (float)((ncode >> 16) & 1);
        float wgt = vp + vn;
        float invnn = shN[mp + dof[d]];
        float cosv = dsum[d] * (invnp * invnn);
        int sn = ncode & 0xFFFF;
        float lab = (sp == sn && sp < 2) ? 1.f : 0.f;
        float diff = cosv - lab;
        acc += wgt * diff * diff;
    }

    // Block reduce (8 warps)
    unsigned mask = 0xFFFFFFFFu;
#pragma unroll
    for (int off = 16; off > 0; off >>= 1) {
        acc += __shfl_down_sync(mask, acc, off);
        cnt += __shfl_down_sync(mask, cnt, off);
        inc |= __shfl_down_sync(mask, inc, off);
    }
    if ((tid & 31) == 0) { sRf[tid >> 5] = acc; sRc[tid >> 5] = cnt; sRi[tid >> 5] = inc; }
    __syncthreads();
    if (tid < 32) {
        float a = (tid < 8) ? sRf[tid] : 0.f;
        int   c = (tid < 8) ? sRc[tid] : 0;
        int   i = (tid < 8) ? sRi[tid] : 0;
#pragma unroll
        for (int off = 4; off > 0; off >>= 1) {
            a += __shfl_down_sync(mask, a, off);
            c += __shfl_down_sync(mask, c, off);
            i |= __shfl_down_sync(mask, i, off);
        }
        if (tid == 0) {
            g_stotal[b * NSTRIP + strip] = a;
            g_scnt [b * NSTRIP + strip] = c;
            g_sinc [b * NSTRIP + strip] = i;
            __threadfence();
            int t = atomicAdd(&g_arrive, 1);
            sLast = (t == NSTRIP * NB - 1) ? 1 : 0;
        }
    }
    __syncthreads();

    // Fused finalize: last block computes the scalar loss.
    if (sLast && tid < NB) {
        float tot = 0.f; int c = 0, i = 0;
        for (int s = 0; s < NSTRIP; s++) {
            tot += g_stotal[tid * NSTRIP + s];
            c   += g_scnt [tid * NSTRIP + s];
            i   |= g_sinc [tid * NSTRIP + s];
        }
        float li = i ? (tot / fmaxf((float)c, 1.f) / 24.f) : 0.f;
        unsigned m8 = 0xFFu;
        int sn = i ? 1 : 0;
#pragma unroll
        for (int off = 4; off > 0; off >>= 1) {
            li += __shfl_down_sync(m8, li, off);
            sn += __shfl_down_sync(m8, sn, off);
        }
        if (tid == 0) {
            out[0] = li / (float)(sn > 0 ? sn : 1);
            g_arrive = 0;   // reset for next graph replay
        }
    }
}

extern "C" void kernel_launch(void* const* d_in, const int* in_sizes, int n_in,
                              void* d_out, int out_size) {
    const float* er  = (const float*)d_in[0];
    const int*   seg = (const int*)d_in[1];
    const int*   gtb = (const int*)d_in[2];

    dim3 gridP(NW / 32, NH / 16, NB * CSPLIT);   // 4 x 8 x 32 = 1024 blocks
    partial_kernel<<<gridP, 128>>>(er);
    dim3 gridE(NSTRIP, NB);                      // 64 x 8 = 512 blocks
    epilogue_kernel<<<gridE, 256>>>(seg, gtb, (float*)d_out);
}

// round 16
// speedup vs baseline: 2.4599x; 2.4599x over previous
#include <cuda_runtime.h>
#include <cuda_fp16.h>
#include <math.h>

// Problem constants
static constexpr int NB = 8, NC = 256, NH = 128, NW = 128;
static constexpr int HW = NH * NW;
static constexpr float EPSF = 1e-8f;

static constexpr int CSPLIT = 4;           // channel slices
static constexpr int CPG = NC / CSPLIT;    // 64 channels per block
static constexpr int CC = 8;               // channels per staged chunk
static constexpr int NCHUNK = CPG / CC;    // 8
static constexpr int SROW = 40;            // smem floats per halo row (16B-aligned)
static constexpr int SPLANE = 18 * SROW;   // 720 floats per channel plane
static constexpr int NSTRIP = 128;         // epilogue: 1-row strips
static constexpr int NEPI = NB * NSTRIP;   // 1024 epilogue blocks

typedef unsigned long long ull;
typedef unsigned int u32;

// Device scratch (dense writes only)
__device__ u32   g_dotsh[CSPLIT][(size_t)NB * HW * 6];  // 12 halves per px
__device__ float g_nsq4[(size_t)NB * HW * 4];           // [pixel][slice]
__device__ float g_stotal[NEPI];
__device__ int   g_scnt [NEPI];
__device__ int   g_sinc [NEPI];
__device__ int   g_arrive;                 // zero-init; reset by last block

__device__ __forceinline__ ull pk(float lo, float hi) {
    ull r;
    asm("mov.b64 %0, {%1, %2};" : "=l"(r) : "f"(lo), "f"(hi));
    return r;
}
__device__ __forceinline__ ull u2(float2 v) { return pk(v.x, v.y); }
__device__ __forceinline__ void upk(ull v, float& lo, float& hi) {
    asm("mov.b64 {%0, %1}, %2;" : "=f"(lo), "=f"(hi) : "l"(v));
}
__device__ __forceinline__ void fma2(ull& a, ull x, ull y) {
    asm("fma.rn.f32x2 %0, %1, %2, %0;" : "+l"(a) : "l"(x), "l"(y));
}
__device__ __forceinline__ u32 h2(float a, float b) {
    __half2 h = __floats2half2_rn(a, b);
    return *(u32*)&h;
}

// ---------------------------------------------------------------------------
// Kernel 1: partial dots + norm^2. cp.async double-buffered channel-plane SMEM.
// Tile 16x32 core (halo 18x[-4,36)), 128 threads = 2x2 px quads.
// Grid (4, 8, NB*CSPLIT) = 1024 blocks.  [EXACT R13 champion path]
// ---------------------------------------------------------------------------
__global__ __launch_bounds__(128, 4) void partial_kernel(const float* __restrict__ er)
{
    __shared__ float sbuf[2][CC * SPLANE];   // 2 x 23040 B

    const int b  = blockIdx.z >> 2;
    const int cs = blockIdx.z & 3;
    const int h0 = blockIdx.y * 16;
    const int w0 = blockIdx.x * 32;
    const int tid = threadIdx.x;
    const int qx = tid & 15;
    const int qy = tid >> 4;

    const float* erblk = er + ((size_t)b * NC + cs * CPG) * HW;

    // ---- precompute staging slots: 1440 cp.async ops = 8ch x 18row x 10grp ----
    int relg[12];   // >=0: plane-relative src offset; <0: zero-fill
    int rels[12];   // >=0: smem byte offset; <0: skip entirely
#pragma unroll
    for (int k = 0; k < 12; k++) {
        int op = tid + k * 128;
        if (op < 1440) {
            int ch  = op / 180;
            int rem = op - ch * 180;
            int row = rem / 10;
            int grp = rem - row * 10;
            int gflat = (h0 + row) * NW + (w0 - 4) + grp * 4;
            bool v = (gflat >= 0) && (gflat <= HW - 4);
            relg[k] = v ? (ch * HW + gflat) : -1;
            rels[k] = (ch * SPLANE + row * SROW + grp * 4) * 4;
        } else {
            relg[k] = -1;
            rels[k] = -1;
        }
    }

    u32 sb0 = (u32)__cvta_generic_to_shared(&sbuf[0][0]);
    u32 sb1 = (u32)__cvta_generic_to_shared(&sbuf[1][0]);

#define ISSUE(CH, SB) {                                                        \
        const float* gb = erblk + (size_t)(CH) * CC * HW;                      \
        _Pragma("unroll")                                                      \
        for (int k = 0; k < 12; k++) {                                         \
            if (rels[k] >= 0) {                                                \
                int rg = relg[k];                                              \
                int sz = (rg >= 0) ? 16 : 0;                                   \
                const float* src = gb + ((rg >= 0) ? rg : 0);                  \
                asm volatile("cp.async.cg.shared.global [%0], [%1], 16, %2;"   \
                             :: "r"((SB) + rels[k]), "l"(src), "r"(sz)         \
                             : "memory");                                      \
            }                                                                  \
        }                                                                      \
        asm volatile("cp.async.commit_group;" ::: "memory");                   \
    }

    ull a0[12], a1[12];
#pragma unroll
    for (int d = 0; d < 12; d++) { a0[d] = 0ull; a1[d] = 0ull; }
    ull selfA = 0ull, selfB = 0ull;

    const int tboff = (2 * qy) * SROW + (2 * qx + 4);

#define COMPUTE(BUF) {                                                         \
        const float* tb = (BUF) + tboff;                                       \
        _Pragma("unroll")                                                      \
        for (int ch = 0; ch < CC; ch++) {                                      \
            const float* pl = tb + ch * SPLANE;                                \
            float2 F0 = *(const float2*)(pl);                                  \
            float2 F2 = *(const float2*)(pl + 2);                              \
            float2 Gm = *(const float2*)(pl + SROW - 2);                       \
            float2 G0 = *(const float2*)(pl + SROW);                           \
            float2 G2 = *(const float2*)(pl + SROW + 2);                       \
            float2 Hm = *(const float2*)(pl + 2 * SROW - 2);                   \
            float2 H0 = *(const float2*)(pl + 2 * SROW);                       \
            float2 H2 = *(const float2*)(pl + 2 * SROW + 2);                   \
            float2 Km = *(const float2*)(pl + 3 * SROW - 2);                   \
            float2 K0 = *(const float2*)(pl + 3 * SROW);                       \
            float2 K2 = *(const float2*)(pl + 3 * SROW + 2);                   \
            ull PP = u2(F0), QQ = u2(G0);                                      \
            ull pF  = pk(F0.y, F2.x);                                          \
            ull pG1 = pk(Gm.y, G0.x), pG2 = pk(G0.y, G2.x);                    \
            ull pH1 = pk(Hm.y, H0.x), pH2 = pk(H0.y, H2.x);                    \
            ull pK1 = pk(Km.y, K0.x), pK2 = pk(K0.y, K2.x);                    \
            ull uF2 = u2(F2), uGm = u2(Gm), uG2 = u2(G2);                      \
            ull uHm = u2(Hm), uH0 = u2(H0), uH2 = u2(H2);                      \
            ull uKm = u2(Km), uK0 = u2(K0), uK2 = u2(K2);                      \
            fma2(selfA, PP, PP);  fma2(selfB, QQ, QQ);                         \
            fma2(a0[0], PP, pF);  fma2(a0[1], PP, uF2);                        \
            fma2(a0[2], PP, uGm); fma2(a0[3], PP, pG1); fma2(a0[4], PP, QQ);   \
            fma2(a0[5], PP, pG2); fma2(a0[6], PP, uG2);                        \
            fma2(a0[7], PP, uHm); fma2(a0[8], PP, pH1); fma2(a0[9], PP, uH0);  \
            fma2(a0[10], PP, pH2); fma2(a0[11], PP, uH2);                      \
            fma2(a1[0], QQ, pG2); fma2(a1[1], QQ, uG2);                        \
            fma2(a1[2], QQ, uHm); fma2(a1[3], QQ, pH1); fma2(a1[4], QQ, uH0);  \
            fma2(a1[5], QQ, pH2); fma2(a1[6], QQ, uH2);                        \
            fma2(a1[7], QQ, uKm); fma2(a1[8], QQ, pK1); fma2(a1[9], QQ, uK0);  \
            fma2(a1[10], QQ, pK2); fma2(a1[11], QQ, uK2);                      \
        }                                                                      \
    }

    ISSUE(0, sb0);
    ISSUE(1, sb1);
#pragma unroll 1
    for (int c = 0; c < NCHUNK; c++) {
        if (c < NCHUNK - 1)
            asm volatile("cp.async.wait_group 1;" ::: "memory");
        else
            asm volatile("cp.async.wait_group 0;" ::: "memory");
        __syncthreads();
        const float* bp = (c & 1) ? &sbuf[1][0] : &sbuf[0][0];
        COMPUTE(bp);
        __syncthreads();
        if (c + 2 < NCHUNK) {
            u32 sb = (c & 1) ? sb1 : sb0;
            ISSUE(c + 2, sb);
        }
    }
#undef ISSUE
#undef COMPUTE

    // ---- writeback as fp16 (dense; each element written exactly once) ----
    const int p00 = (h0 + 2 * qy) * NW + (w0 + 2 * qx);
    u32* dbase = g_dotsh[cs] + (size_t)b * HW * 6;
    float v0[12], v1[12], v2[12], v3[12];
#pragma unroll
    for (int d = 0; d < 12; d++) {
        upk(a0[d], v0[d], v1[d]);
        upk(a1[d], v2[d], v3[d]);
    }
#define ST12H(P, V) {                                                          \
        u32* dst = dbase + (size_t)(P) * 6;                                    \
        *(uint2*)(dst)     = make_uint2(h2(V[0], V[1]),  h2(V[2],  V[3]));     \
        *(uint2*)(dst + 2) = make_uint2(h2(V[4], V[5]),  h2(V[6],  V[7]));     \
        *(uint2*)(dst + 4) = make_uint2(h2(V[8], V[9]),  h2(V[10], V[11]));    \
    }
    ST12H(p00,          v0);
    ST12H(p00 + 1,      v1);
    ST12H(p00 + NW,     v2);
    ST12H(p00 + NW + 1, v3);
#undef ST12H
    float s0, s1, s2, s3;
    upk(selfA, s0, s1);
    upk(selfB, s2, s3);
    float* nptr = g_nsq4 + ((size_t)b * HW + p00) * 4 + cs;
    nptr[0]           = s0;
    nptr[4]           = s1;
    nptr[NW * 4]      = s2;
    nptr[NW * 4 + 4]  = s3;
}

// ---------------------------------------------------------------------------
// Kernel 2: epilogue. 1-row strips, 2 threads per pixel (d split 6/6).
// Grid (128, NB) = 1024 blocks x 256 threads (8192 warps = 86% of chip).
// ---------------------------------------------------------------------------
__global__ __launch_bounds__(256) void epilogue_kernel(
    const int* __restrict__ seg, const int* __restrict__ gtb,
    float* __restrict__ out)
{
    __shared__ float shN[3 * 132];     // INVERSE norms (rows h0..h0+2)
    __shared__ int   shL[3 * 132];
    __shared__ float sRf[8];
    __shared__ int   sRc[8], sRi[8], sLast;
    __shared__ float sLi[8];
    __shared__ int   sIn[8];

    const int h0  = blockIdx.x;        // 1-row strip
    const int b   = blockIdx.y;
    const int tid = threadIdx.x;
    const int* segb = seg + b * HW;
    const int* gtbb = gtb + b * HW;

    // Stage inverse norms + label codes: rows [h0, h0+3), cols [-2, 130)
    for (int i = tid; i < 3 * 132; i += 256) {
        int r = i / 132, c = i - r * 132;
        int gh = h0 + r, gw = c - 2;
        float inv = 1.f;
        int code = 0x7FFF;
        if (gh < NH && gw >= 0 && gw < NW) {
            size_t idx = (size_t)b * HW + gh * NW + gw;
            float4 n4 = *(const float4*)(g_nsq4 + idx * 4);
            float ns = (n4.x + n4.y) + (n4.z + n4.w);
            inv = 1.f / fmaxf(sqrtf(ns), EPSF);
            int li = gh * NW + gw;
            int s = segb[li], g = gtbb[li];
            int s0v = (s == 255) ? 0 : s;
            int g0v = (g == 255) ? 0 : g;
            bool fg    = (s0v * g0v > 0);
            bool inter = (gh >= 2 && gh < NH - 2 && gw >= 2 && gw < NW - 2);
            code = (s & 0xFFFF) | ((fg && inter) ? 0x10000 : 0) | (fg ? 0x20000 : 0);
        }
        shN[i] = inv;
        shL[i] = code;
    }
    __syncthreads();

    const int tx  = tid & 127;          // pixel column
    const bool lo = (tid < 128);        // low half: d0..5 (words 0..2)
    const int wbase = lo ? 0 : 3;       // first dot-word
    const int p   = h0 * NW + tx;

    // Gather 6 dot values (fp16 words wbase..wbase+2, summed over 4 slices)
    float dsum[6];
#pragma unroll
    for (int j = 0; j < 6; j++) dsum[j] = 0.f;
    {
        const size_t off = ((size_t)b * HW + p) * 6 + wbase;
#pragma unroll
        for (int cs = 0; cs < CSPLIT; cs++) {
            const u32* sp = g_dotsh[cs] + off;
            u32 wa = sp[0], wb = sp[1], wc = sp[2];
            float2 f;
            f = __half22float2(*(__half2*)&wa); dsum[0] += f.x; dsum[1] += f.y;
            f = __half22float2(*(__half2*)&wb); dsum[2] += f.x; dsum[3] += f.y;
            f = __half22float2(*(__half2*)&wc); dsum[4] += f.x; dsum[5] += f.y;
        }
    }

    const int dof[12] = {1, 2,
                         132 - 2, 132 - 1, 132, 132 + 1, 132 + 2,
                         264 - 2, 264 - 1, 264, 264 + 1, 264 + 2};
    const int dbase = lo ? 0 : 6;
    const int mp = tx + 2;              // core pixel at staged row 0

    int pcode = shL[mp];
    float vp  = (float)((pcode >> 16) & 1);
    int   cnt = lo ? ((pcode >> 16) & 1) : 0;   // count once per pixel
    int   inc = lo ? ((pcode >> 17) & 1) : 0;
    int   sp2 = pcode & 0xFFFF;
    float invnp = shN[mp];

    float acc = 0.f;
#pragma unroll
    for (int j = 0; j < 6; j++) {
        int o = dof[dbase + j];
        int ncode = shL[mp + o];
        float vn  = (float)((ncode >> 16) & 1);
        float wgt = vp + vn;
        float invnn = shN[mp + o];
        float cosv = dsum[j] * (invnp * invnn);
        int sn = ncode & 0xFFFF;
        float lab = (sp2 == sn && sp2 < 2) ? 1.f : 0.f;
        float diff = cosv - lab;
        acc += wgt * diff * diff;
    }

    // Block reduce (8 warps)
    unsigned mask = 0xFFFFFFFFu;
#pragma unroll
    for (int off = 16; off > 0; off >>= 1) {
        acc += __shfl_down_sync(mask, acc, off);
        cnt += __shfl_down_sync(mask, cnt, off);
        inc |= __shfl_down_sync(mask, inc, off);
    }
    if ((tid & 31) == 0) { sRf[tid >> 5] = acc; sRc[tid >> 5] = cnt; sRi[tid >> 5] = inc; }
    __syncthreads();
    if (tid < 32) {
        float a = (tid < 8) ? sRf[tid] : 0.f;
        int   c = (tid < 8) ? sRc[tid] : 0;
        int   i = (tid < 8) ? sRi[tid] : 0;
#pragma unroll
        for (int off = 4; off > 0; off >>= 1) {
            a += __shfl_down_sync(mask, a, off);
            c += __shfl_down_sync(mask, c, off);
            i |= __shfl_down_sync(mask, i, off);
        }
        if (tid == 0) {
            g_stotal[b * NSTRIP + h0] = a;
            g_scnt [b * NSTRIP + h0] = c;
            g_sinc [b * NSTRIP + h0] = i;
            __threadfence();
            int t = atomicAdd(&g_arrive, 1);
            sLast = (t == NEPI - 1) ? 1 : 0;
        }
    }
    __syncthreads();
    if (!sLast) return;

    // ---- finalize (exactly one block; 8 warps, one per image) ----
    {
        int img = tid >> 5, lane = tid & 31;
        float tot = 0.f; int c = 0, i = 0;
        for (int s = lane; s < NSTRIP; s += 32) {
            tot += g_stotal[img * NSTRIP + s];
            c   += g_scnt [img * NSTRIP + s];
            i   |= g_sinc [img * NSTRIP + s];
        }
#pragma unroll
        for (int off = 16; off > 0; off >>= 1) {
            tot += __shfl_down_sync(mask, tot, off);
            c   += __shfl_down_sync(mask, c, off);
            i   |= __shfl_down_sync(mask, i, off);
        }
        if (lane == 0) {
            sLi[img] = i ? (tot / fmaxf((float)c, 1.f) / 24.f) : 0.f;
            sIn[img] = i ? 1 : 0;
        }
    }
    __syncthreads();
    if (tid == 0) {
        float sum = 0.f; int sn = 0;
        for (int bb = 0; bb < NB; bb++) { sum += sLi[bb]; sn += sIn[bb]; }
        out[0] = sum / (float)(sn > 0 ? sn : 1);
        g_arrive = 0;   // reset for next graph replay
    }
}

extern "C" void kernel_launch(void* const* d_in, const int* in_sizes, int n_in,
                              void* d_out, int out_size) {
    const float* er  = (const float*)d_in[0];
    const int*   seg = (const int*)d_in[1];
    const int*   gtb = (const int*)d_in[2];

    dim3 gridP(NW / 32, NH / 16, NB * CSPLIT);   // 4 x 8 x 32 = 1024 blocks
    partial_kernel<<<gridP, 128>>>(er);
    dim3 gridE(NSTRIP, NB);                      // 128 x 8 = 1024 blocks
    epilogue_kernel<<<gridE, 256>>>(seg, gtb, (float*)d_out);
}

// round 17
// speedup vs baseline: 2.6238x; 1.0666x over previous
#include <cuda_runtime.h>
#include <cuda_fp16.h>
#include <math.h>

// Problem constants
static constexpr int NB = 8, NC = 256, NH = 128, NW = 128;
static constexpr int HW = NH * NW;
static constexpr float EPSF = 1e-8f;

static constexpr int CSPLIT = 4;           // channel slices
static constexpr int CPG = NC / CSPLIT;    // 64 channels per block
static constexpr int CC = 4;               // channels per staged chunk
static constexpr int NCHUNK = CPG / CC;    // 16
static constexpr int SROW = 40;            // smem floats per halo row (16B-aligned)
static constexpr int SPLANE = 18 * SROW;   // 720 floats per channel plane
static constexpr int CHUNKF = CC * SPLANE; // 2880 floats per chunk buffer
static constexpr int NSTRIP = 128;         // epilogue: 1-row strips
static constexpr int NEPI = NB * NSTRIP;   // 1024 epilogue blocks

typedef unsigned long long ull;
typedef unsigned int u32;

// Device scratch (dense writes only)
__device__ u32   g_dotsh[CSPLIT][(size_t)NB * HW * 6];  // 12 halves per px
__device__ float g_nsq4[(size_t)NB * HW * 4];           // [pixel][slice]
__device__ float g_stotal[NEPI];
__device__ int   g_scnt [NEPI];
__device__ int   g_sinc [NEPI];
__device__ int   g_arrive;                 // zero-init; reset by last block

__device__ __forceinline__ ull pk(float lo, float hi) {
    ull r;
    asm("mov.b64 %0, {%1, %2};" : "=l"(r) : "f"(lo), "f"(hi));
    return r;
}
__device__ __forceinline__ ull u2(float2 v) { return pk(v.x, v.y); }
__device__ __forceinline__ void upk(ull v, float& lo, float& hi) {
    asm("mov.b64 {%0, %1}, %2;" : "=f"(lo), "=f"(hi) : "l"(v));
}
__device__ __forceinline__ void fma2(ull& a, ull x, ull y) {
    asm("fma.rn.f32x2 %0, %1, %2, %0;" : "+l"(a) : "l"(x), "l"(y));
}
__device__ __forceinline__ u32 h2(float a, float b) {
    __half2 h = __floats2half2_rn(a, b);
    return *(u32*)&h;
}

// ---------------------------------------------------------------------------
// Kernel 1: partial dots + norm^2. cp.async 3-buffer ring, CC=4 chunks.
// Tile 16x32 core (halo 18x[-4,36)), 128 threads = 2x2 px quads, 5 blocks/SM.
// Grid (4, 8, NB*CSPLIT) = 1024 blocks.
// ---------------------------------------------------------------------------
__global__ __launch_bounds__(128, 5) void partial_kernel(const float* __restrict__ er)
{
    __shared__ float sbuf[3 * CHUNKF];   // 3 x 11520 B = 34560 B

    const int b  = blockIdx.z >> 2;
    const int cs = blockIdx.z & 3;
    const int h0 = blockIdx.y * 16;
    const int w0 = blockIdx.x * 32;
    const int tid = threadIdx.x;
    const int qx = tid & 15;
    const int qy = tid >> 4;

    const float* erblk = er + ((size_t)b * NC + cs * CPG) * HW;

    // ---- staging slots: 720 cp.async ops/chunk = 4ch x 18row x 10grp ----
    int relg[6];   // >=0: plane-relative src offset; <0: zero-fill
    int rels[6];   // >=0: smem byte offset; <0: skip entirely
#pragma unroll
    for (int k = 0; k < 6; k++) {
        int op = tid + k * 128;
        if (op < 720) {
            int ch  = op / 180;
            int rem = op - ch * 180;
            int row = rem / 10;
            int grp = rem - row * 10;
            int gflat = (h0 + row) * NW + (w0 - 4) + grp * 4;
            bool v = (gflat >= 0) && (gflat <= HW - 4);
            relg[k] = v ? (ch * HW + gflat) : -1;
            rels[k] = (ch * SPLANE + row * SROW + grp * 4) * 4;
        } else {
            relg[k] = -1;
            rels[k] = -1;
        }
    }

    const u32 sbB = (u32)__cvta_generic_to_shared(&sbuf[0]);

#define ISSUE(CH, SB) {                                                        \
        const float* gb = erblk + (size_t)(CH) * CC * HW;                      \
        _Pragma("unroll")                                                      \
        for (int k = 0; k < 6; k++) {                                          \
            if (rels[k] >= 0) {                                                \
                int rg = relg[k];                                              \
                int sz = (rg >= 0) ? 16 : 0;                                   \
                const float* src = gb + ((rg >= 0) ? rg : 0);                  \
                asm volatile("cp.async.cg.shared.global [%0], [%1], 16, %2;"   \
                             :: "r"((SB) + rels[k]), "l"(src), "r"(sz)         \
                             : "memory");                                      \
            }                                                                  \
        }                                                                      \
        asm volatile("cp.async.commit_group;" ::: "memory");                   \
    }

    ull a0[12], a1[12];
#pragma unroll
    for (int d = 0; d < 12; d++) { a0[d] = 0ull; a1[d] = 0ull; }
    ull selfA = 0ull, selfB = 0ull;

    const int tboff = (2 * qy) * SROW + (2 * qx + 4);

#define COMPUTE(BUF) {                                                         \
        const float* tb = (BUF) + tboff;                                       \
        _Pragma("unroll")                                                      \
        for (int ch = 0; ch < CC; ch++) {                                      \
            const float* pl = tb + ch * SPLANE;                                \
            float2 F0 = *(const float2*)(pl);                                  \
            float2 F2 = *(const float2*)(pl + 2);                              \
            float2 Gm = *(const float2*)(pl + SROW - 2);                       \
            float2 G0 = *(const float2*)(pl + SROW);                           \
            float2 G2 = *(const float2*)(pl + SROW + 2);                       \
            float2 Hm = *(const float2*)(pl + 2 * SROW - 2);                   \
            float2 H0 = *(const float2*)(pl + 2 * SROW);                       \
            float2 H2 = *(const float2*)(pl + 2 * SROW + 2);                   \
            float2 Km = *(const float2*)(pl + 3 * SROW - 2);                   \
            float2 K0 = *(const float2*)(pl + 3 * SROW);                       \
            float2 K2 = *(const float2*)(pl + 3 * SROW + 2);                   \
            ull PP = u2(F0), QQ = u2(G0);                                      \
            ull pF  = pk(F0.y, F2.x);                                          \
            ull pG1 = pk(Gm.y, G0.x), pG2 = pk(G0.y, G2.x);                    \
            ull pH1 = pk(Hm.y, H0.x), pH2 = pk(H0.y, H2.x);                    \
            ull pK1 = pk(Km.y, K0.x), pK2 = pk(K0.y, K2.x);                    \
            ull uF2 = u2(F2), uGm = u2(Gm), uG2 = u2(G2);                      \
            ull uHm = u2(Hm), uH0 = u2(H0), uH2 = u2(H2);                      \
            ull uKm = u2(Km), uK0 = u2(K0), uK2 = u2(K2);                      \
            fma2(selfA, PP, PP);  fma2(selfB, QQ, QQ);                         \
            fma2(a0[0], PP, pF);  fma2(a0[1], PP, uF2);                        \
            fma2(a0[2], PP, uGm); fma2(a0[3], PP, pG1); fma2(a0[4], PP, QQ);   \
            fma2(a0[5], PP, pG2); fma2(a0[6], PP, uG2);                        \
            fma2(a0[7], PP, uHm); fma2(a0[8], PP, pH1); fma2(a0[9], PP, uH0);  \
            fma2(a0[10], PP, pH2); fma2(a0[11], PP, uH2);                      \
            fma2(a1[0], QQ, pG2); fma2(a1[1], QQ, uG2);                        \
            fma2(a1[2], QQ, uHm); fma2(a1[3], QQ, pH1); fma2(a1[4], QQ, uH0);  \
            fma2(a1[5], QQ, pH2); fma2(a1[6], QQ, uH2);                        \
            fma2(a1[7], QQ, uKm); fma2(a1[8], QQ, pK1); fma2(a1[9], QQ, uK0);  \
            fma2(a1[10], QQ, pK2); fma2(a1[11], QQ, uK2);                      \
        }                                                                      \
    }

    // ---- pipeline: 3-buffer ring, depth 2, ONE barrier per chunk ----
    ISSUE(0, sbB);
    ISSUE(1, sbB + CHUNKF * 4);
#pragma unroll 1
    for (int c = 0; c < NCHUNK; c++) {
        if (c < NCHUNK - 1)
            asm volatile("cp.async.wait_group 1;" ::: "memory");
        else
            asm volatile("cp.async.wait_group 0;" ::: "memory");
        __syncthreads();   // buffer c ready for all; buffer (c+2)%3 free for all
        if (c + 2 < NCHUNK) {
            int bi = c + 2 - ((c + 2) / 3) * 3;
            ISSUE(c + 2, sbB + bi * (CHUNKF * 4));
        }
        int ci = c - (c / 3) * 3;
        COMPUTE(&sbuf[0] + ci * CHUNKF);
    }
#undef ISSUE
#undef COMPUTE

    // ---- writeback as fp16 (dense; each element written exactly once) ----
    const int p00 = (h0 + 2 * qy) * NW + (w0 + 2 * qx);
    u32* dbase = g_dotsh[cs] + (size_t)b * HW * 6;
    float v0[12], v1[12], v2[12], v3[12];
#pragma unroll
    for (int d = 0; d < 12; d++) {
        upk(a0[d], v0[d], v1[d]);
        upk(a1[d], v2[d], v3[d]);
    }
#define ST12H(P, V) {                                                          \
        u32* dst = dbase + (size_t)(P) * 6;                                    \
        *(uint2*)(dst)     = make_uint2(h2(V[0], V[1]),  h2(V[2],  V[3]));     \
        *(uint2*)(dst + 2) = make_uint2(h2(V[4], V[5]),  h2(V[6],  V[7]));     \
        *(uint2*)(dst + 4) = make_uint2(h2(V[8], V[9]),  h2(V[10], V[11]));    \
    }
    ST12H(p00,          v0);
    ST12H(p00 + 1,      v1);
    ST12H(p00 + NW,     v2);
    ST12H(p00 + NW + 1, v3);
#undef ST12H
    float s0, s1, s2, s3;
    upk(selfA, s0, s1);
    upk(selfB, s2, s3);
    float* nptr = g_nsq4 + ((size_t)b * HW + p00) * 4 + cs;
    nptr[0]           = s0;
    nptr[4]           = s1;
    nptr[NW * 4]      = s2;
    nptr[NW * 4 + 4]  = s3;
}

// ---------------------------------------------------------------------------
// Kernel 2: epilogue. 1-row strips, 2 threads per pixel.  [unchanged from R16]
// Grid (128, NB) = 1024 blocks x 256 threads.
// ---------------------------------------------------------------------------
__global__ __launch_bounds__(256) void epilogue_kernel(
    const int* __restrict__ seg, const int* __restrict__ gtb,
    float* __restrict__ out)
{
    __shared__ float shN[3 * 132];     // INVERSE norms (rows h0..h0+2)
    __shared__ int   shL[3 * 132];
    __shared__ float sRf[8];
    __shared__ int   sRc[8], sRi[8], sLast;
    __shared__ float sLi[8];
    __shared__ int   sIn[8];

    const int h0  = blockIdx.x;        // 1-row strip
    const int b   = blockIdx.y;
    const int tid = threadIdx.x;
    const int* segb = seg + b * HW;
    const int* gtbb = gtb + b * HW;

    // Stage inverse norms + label codes: rows [h0, h0+3), cols [-2, 130)
    for (int i = tid; i < 3 * 132; i += 256) {
        int r = i / 132, c = i - r * 132;
        int gh = h0 + r, gw = c - 2;
        float inv = 1.f;
        int code = 0x7FFF;
        if (gh < NH && gw >= 0 && gw < NW) {
            size_t idx = (size_t)b * HW + gh * NW + gw;
            float4 n4 = *(const float4*)(g_nsq4 + idx * 4);
            float ns = (n4.x + n4.y) + (n4.z + n4.w);
            inv = 1.f / fmaxf(sqrtf(ns), EPSF);
            int li = gh * NW + gw;
            int s = segb[li], g = gtbb[li];
            int s0v = (s == 255) ? 0 : s;
            int g0v = (g == 255) ? 0 : g;
            bool fg    = (s0v * g0v > 0);
            bool inter = (gh >= 2 && gh < NH - 2 && gw >= 2 && gw < NW - 2);
            code = (s & 0xFFFF) | ((fg && inter) ? 0x10000 : 0) | (fg ? 0x20000 : 0);
        }
        shN[i] = inv;
        shL[i] = code;
    }
    __syncthreads();

    const int tx  = tid & 127;          // pixel column
    const bool lo = (tid < 128);        // low half: d0..5 (words 0..2)
    const int wbase = lo ? 0 : 3;       // first dot-word
    const int p   = h0 * NW + tx;

    // Gather 6 dot values (fp16 words wbase..wbase+2, summed over 4 slices)
    float dsum[6];
#pragma unroll
    for (int j = 0; j < 6; j++) dsum[j] = 0.f;
    {
        const size_t off = ((size_t)b * HW + p) * 6 + wbase;
#pragma unroll
        for (int cs = 0; cs < CSPLIT; cs++) {
            const u32* sp = g_dotsh[cs] + off;
            u32 wa = sp[0], wb = sp[1], wc = sp[2];
            float2 f;
            f = __half22float2(*(__half2*)&wa); dsum[0] += f.x; dsum[1] += f.y;
            f = __half22float2(*(__half2*)&wb); dsum[2] += f.x; dsum[3] += f.y;
            f = __half22float2(*(__half2*)&wc); dsum[4] += f.x; dsum[5] += f.y;
        }
    }

    const int dof[12] = {1, 2,
                         132 - 2, 132 - 1, 132, 132 + 1, 132 + 2,
                         264 - 2, 264 - 1, 264, 264 + 1, 264 + 2};
    const int dbase = lo ? 0 : 6;
    const int mp = tx + 2;              // core pixel at staged row 0

    int pcode = shL[mp];
    float vp  = (float)((pcode >> 16) & 1);
    int   cnt = lo ? ((pcode >> 16) & 1) : 0;   // count once per pixel
    int   inc = lo ? ((pcode >> 17) & 1) : 0;
    int   sp2 = pcode & 0xFFFF;
    float invnp = shN[mp];

    float acc = 0.f;
#pragma unroll
    for (int j = 0; j < 6; j++) {
        int o = dof[dbase + j];
        int ncode = shL[mp + o];
        float vn  = (float)((ncode >> 16) & 1);
        float wgt = vp + vn;
        float invnn = shN[mp + o];
        float cosv = dsum[j] * (invnp * invnn);
        int sn = ncode & 0xFFFF;
        float lab = (sp2 == sn && sp2 < 2) ? 1.f : 0.f;
        float diff = cosv - lab;
        acc += wgt * diff * diff;
    }

    // Block reduce (8 warps)
    unsigned mask = 0xFFFFFFFFu;
#pragma unroll
    for (int off = 16; off > 0; off >>= 1) {
        acc += __shfl_down_sync(mask, acc, off);
        cnt += __shfl_down_sync(mask, cnt, off);
        inc |= __shfl_down_sync(mask, inc, off);
    }
    if ((tid & 31) == 0) { sRf[tid >> 5] = acc; sRc[tid >> 5] = cnt; sRi[tid >> 5] = inc; }
    __syncthreads();
    if (tid < 32) {
        float a = (tid < 8) ? sRf[tid] : 0.f;
        int   c = (tid < 8) ? sRc[tid] : 0;
        int   i = (tid < 8) ? sRi[tid] : 0;
#pragma unroll
        for (int off = 4; off > 0; off >>= 1) {
            a += __shfl_down_sync(mask, a, off);
            c += __shfl_down_sync(mask, c, off);
            i |= __shfl_down_sync(mask, i, off);
        }
        if (tid == 0) {
            g_stotal[b * NSTRIP + h0] = a;
            g_scnt [b * NSTRIP + h0] = c;
            g_sinc [b * NSTRIP + h0] = i;
            __threadfence();
            int t = atomicAdd(&g_arrive, 1);
            sLast = (t == NEPI - 1) ? 1 : 0;
        }
    }
    __syncthreads();
    if (!sLast) return;

    // ---- finalize (exactly one block; 8 warps, one per image) ----
    {
        int img = tid >> 5, lane = tid & 31;
        float tot = 0.f; int c = 0, i = 0;
        for (int s = lane; s < NSTRIP; s += 32) {
            tot += g_stotal[img * NSTRIP + s];
            c   += g_scnt [img * NSTRIP + s];
            i   |= g_sinc [img * NSTRIP + s];
        }
#pragma unroll
        for (int off = 16; off > 0; off >>= 1) {
            tot += __shfl_down_sync(mask, tot, off);
            c   += __shfl_down_sync(mask, c, off);
            i   |= __shfl_down_sync(mask, i, off);
        }
        if (lane == 0) {
            sLi[img] = i ? (tot / fmaxf((float)c, 1.f) / 24.f) : 0.f;
            sIn[img] = i ? 1 : 0;
        }
    }
    __syncthreads();
    if (tid == 0) {
        float sum = 0.f; int sn = 0;
        for (int bb = 0; bb < NB; bb++) { sum += sLi[bb]; sn += sIn[bb]; }
        out[0] = sum / (float)(sn > 0 ? sn : 1);
        g_arrive = 0;   // reset for next graph replay
    }
}

extern "C" void kernel_launch(void* const* d_in, const int* in_sizes, int n_in,
                              void* d_out, int out_size) {
    const float* er  = (const float*)d_in[0];
    const int*   seg = (const int*)d_in[1];
    const int*   gtb = (const int*)d_in[2];

    dim3 gridP(NW / 32, NH / 16, NB * CSPLIT);   // 4 x 8 x 32 = 1024 blocks
    partial_kernel<<<gridP, 128>>>(er);
    dim3 gridE(NSTRIP, NB);                      // 128 x 8 = 1024 blocks
    epilogue_kernel<<<gridE, 256>>>(seg, gtb, (float*)d_out);
}